// round 9
// baseline (speedup 1.0000x reference)
#include <cuda_runtime.h>
#include <cuda_bf16.h>

// Problem shapes:
//   node_emb      [100000, 64] f32
//   hyperedge_emb [ 50000, 64] f32
//   h             [200000]      i32
//   X             [200000, 8]   i32
//   out           [200000, 2]   f32
//
// Layout: 16 lanes per candidate (lane owns one float4 = 4 dims, held as a
// ulonglong2 so packed f32x2 pairs come straight out of LDG.128),
// 2 candidates per warp, 128 threads/block, PERSISTENT grid-stride loop
// (1184 CTAs = 148 SMs x 8 resident) to amortize CTA launch overhead.
// Dot products use Blackwell packed f32x2 FMA. Cross-lane sums use
// recursive-halving reduce-scatter (15 shuffles / 16-value group); the
// induced bit-reversal permutation is harmless since every group feeds a
// min. X row loaded as 2x int4 (uniform within segment -> L1 broadcast).
// Registers at 64 (launch_bounds occ=8) -> 32 warps/SM (proven optimum).

#define SET_SIZE 8
#define EMB_DIM  64
#define ROW_BYTES 256
#define FULL 0xffffffffu
#define PAD_BIG 1e30f

typedef unsigned long long u64;

__device__ __forceinline__ u64 mul2(u64 a, u64 b) {
    u64 r;
    asm("mul.rn.f32x2 %0, %1, %2;" : "=l"(r) : "l"(a), "l"(b));
    return r;
}
__device__ __forceinline__ u64 fma2(u64 a, u64 b, u64 c) {
    u64 r;
    asm("fma.rn.f32x2 %0, %1, %2, %3;" : "=l"(r) : "l"(a), "l"(b), "l"(c));
    return r;
}

// dot of two 4-dim slices held as packed f32x2 pairs: 2 packed ops + 1 FADD.
__device__ __forceinline__ float dot4p(const ulonglong2& a, const ulonglong2& b) {
    u64 p = mul2(a.x, b.x);
    p = fma2(a.y, b.y, p);
    float lo = __uint_as_float((unsigned)p);
    float hi = __uint_as_float((unsigned)(p >> 32));
    return lo + hi;
}

__device__ __forceinline__ float fast_sigmoid(float x) {
    return 1.0f / (1.0f + __expf(-x));
}

__device__ __forceinline__ ulonglong2 ldg16_off(const char* base, unsigned byte_off) {
    return __ldg(reinterpret_cast<const ulonglong2*>(base + byte_off));
}

// Reduce-scatter 16 values across the 16-lane segment (sub = lane & 15).
// Afterwards each lane holds the full 16-lane sum of value index bitrev4(sub).
__device__ __forceinline__ float rs16(float (&cur)[16], int sub) {
    #pragma unroll
    for (int j = 0; j < 8; j++) {
        float send = (sub & 1) ? cur[j] : cur[j + 8];
        float keep = (sub & 1) ? cur[j + 8] : cur[j];
        cur[j] = keep + __shfl_xor_sync(FULL, send, 1);
    }
    #pragma unroll
    for (int j = 0; j < 4; j++) {
        float send = (sub & 2) ? cur[j] : cur[j + 4];
        float keep = (sub & 2) ? cur[j + 4] : cur[j];
        cur[j] = keep + __shfl_xor_sync(FULL, send, 2);
    }
    #pragma unroll
    for (int j = 0; j < 2; j++) {
        float send = (sub & 4) ? cur[j] : cur[j + 2];
        float keep = (sub & 4) ? cur[j + 2] : cur[j];
        cur[j] = keep + __shfl_xor_sync(FULL, send, 4);
    }
    {
        float send = (sub & 8) ? cur[0] : cur[1];
        float keep = (sub & 8) ? cur[1] : cur[0];
        cur[0] = keep + __shfl_xor_sync(FULL, send, 8);
    }
    return cur[0];
}

__global__ __launch_bounds__(128, 8)
void hyperedge_score_kernel(const float* __restrict__ node_emb,
                            const float* __restrict__ hyper_emb,
                            const int* __restrict__ h,
                            const int* __restrict__ X,
                            float* __restrict__ out,
                            int n_cand, int n_groups)
{
    const int lane = threadIdx.x & 31;
    const int warp = threadIdx.x >> 5;
    const int seg  = lane >> 4;   // candidate within warp (0..1)
    const int sub  = lane & 15;   // float4 slice id      (0..15)

    const char* nbase = reinterpret_cast<const char*>(node_emb);
    const char* hbase = reinterpret_cast<const char*>(hyper_emb);
    const unsigned lane_off = (unsigned)(sub * 16);   // float4 within row

    // Persistent grid-stride loop over groups of 8 candidates.
    for (int grp = blockIdx.x; grp < n_groups; grp += gridDim.x) {
        int e = (grp * 4 + warp) * 2 + seg;
        int ec = min(e, n_cand - 1);

        // Each lane loads its candidate's full X row: 2x int4, uniform
        // within the 16-lane segment (L1 broadcast).
        const int4* xrow = reinterpret_cast<const int4*>(X + ec * SET_SIZE);
        int4 xa = __ldg(xrow);
        int4 xb = __ldg(xrow + 1);
        int h_idx = __ldg(h + ec);

        // Gather src slice + 8 node slices; all loads issued up front.
        ulonglong2 s = ldg16_off(hbase, (unsigned)h_idx * ROW_BYTES + lane_off);

        ulonglong2 nv[SET_SIZE];
        nv[0] = ldg16_off(nbase, (unsigned)xa.x * ROW_BYTES + lane_off);
        nv[1] = ldg16_off(nbase, (unsigned)xa.y * ROW_BYTES + lane_off);
        nv[2] = ldg16_off(nbase, (unsigned)xa.z * ROW_BYTES + lane_off);
        nv[3] = ldg16_off(nbase, (unsigned)xa.w * ROW_BYTES + lane_off);
        nv[4] = ldg16_off(nbase, (unsigned)xb.x * ROW_BYTES + lane_off);
        nv[5] = ldg16_off(nbase, (unsigned)xb.y * ROW_BYTES + lane_off);
        nv[6] = ldg16_off(nbase, (unsigned)xb.z * ROW_BYTES + lane_off);
        nv[7] = ldg16_off(nbase, (unsigned)xb.w * ROW_BYTES + lane_off);

        float cur[16];

        // ---- group 0: star (indices 0..7) + diagonal (indices 8..15) ----
        #pragma unroll
        for (int t = 0; t < SET_SIZE; t++) cur[t] = dot4p(s, nv[t]);
        #pragma unroll
        for (int t = 0; t < SET_SIZE; t++) cur[8 + t] = dot4p(nv[t], nv[t]);

        float v = rs16(cur, sub);
        // bitrev: even lanes hold star sums, odd lanes hold diagonal sums.
        v = fminf(v, __shfl_xor_sync(FULL, v, 2));
        v = fminf(v, __shfl_xor_sync(FULL, v, 4));
        v = fminf(v, __shfl_xor_sync(FULL, v, 8));
        float star_min = v;                              // valid on even lanes
        float diag_min = __shfl_xor_sync(FULL, v, 1);    // odd lanes' min -> even

        // ---- off-diagonal pairs: 28 dots in 2 chunks of 16 ----
        {
            const int PA0[16] = {0,0,0,0,0,0,0, 1,1,1,1,1,1, 2,2,2};
            const int PB0[16] = {1,2,3,4,5,6,7, 2,3,4,5,6,7, 3,4,5};
            #pragma unroll
            for (int k = 0; k < 16; k++) cur[k] = dot4p(nv[PA0[k]], nv[PB0[k]]);
        }
        float p0 = rs16(cur, sub);

        {
            const int PA1[12] = {2,2, 3,3,3,3, 4,4,4, 5,5, 6};
            const int PB1[12] = {6,7, 4,5,6,7, 5,6,7, 6,7, 7};
            #pragma unroll
            for (int k = 0; k < 12; k++) cur[k] = dot4p(nv[PA1[k]], nv[PB1[k]]);
            #pragma unroll
            for (int k = 12; k < 16; k++) cur[k] = PAD_BIG;
        }
        float p1 = rs16(cur, sub);

        float pmin = fminf(p0, p1);
        pmin = fminf(pmin, __shfl_xor_sync(FULL, pmin, 1));
        pmin = fminf(pmin, __shfl_xor_sync(FULL, pmin, 2));
        pmin = fminf(pmin, __shfl_xor_sync(FULL, pmin, 4));
        pmin = fminf(pmin, __shfl_xor_sync(FULL, pmin, 8));

        if (e < n_cand && sub == 0) {
            float clique = fminf(diag_min, pmin);
            float2 o = make_float2(fast_sigmoid(star_min), fast_sigmoid(clique));
            reinterpret_cast<float2*>(out)[e] = o;
        }
    }
}

extern "C" void kernel_launch(void* const* d_in, const int* in_sizes, int n_in,
                              void* d_out, int out_size) {
    const float* node_emb  = (const float*)d_in[0];
    const float* hyper_emb = (const float*)d_in[1];
    const int*   h         = (const int*)d_in[2];
    const int*   X         = (const int*)d_in[3];
    float*       out       = (float*)d_out;

    const int n_cand = in_sizes[2];

    const int cands_per_block = 8;    // 4 warps * 2 candidates
    const int n_groups = (n_cand + cands_per_block - 1) / cands_per_block;

    // Persistent grid: 148 SMs x 8 resident CTAs.
    int blocks = 148 * 8;
    if (blocks > n_groups) blocks = n_groups;

    hyperedge_score_kernel<<<blocks, 128>>>(node_emb, hyper_emb, h, X, out,
                                            n_cand, n_groups);
}

// round 10
// speedup vs baseline: 1.0816x; 1.0816x over previous
#include <cuda_runtime.h>
#include <cuda_bf16.h>

// Problem shapes:
//   node_emb      [100000, 64] f32
//   hyperedge_emb [ 50000, 64] f32
//   h             [200000]      i32
//   X             [200000, 8]   i32
//   out           [200000, 2]   f32
//
// Layout: 16 lanes per candidate (lane owns one float4 = 4 dims as a
// ulonglong2 for packed f32x2 math), 2 candidates per warp-phase,
// TWO software-pipelined phases per warp (A and B): all of B's gathers are
// issued before A's compute, so A's dot/reduction work (~200 cyc) hides
// B's L2-gather latency. 128 threads/block -> 16 candidates/block.
// Cross-lane sums use recursive-halving reduce-scatter (15 shuffles per
// 16-value group); bit-reversal permutation harmless (feeds mins).

#define SET_SIZE 8
#define EMB_DIM  64
#define ROW_BYTES 256
#define FULL 0xffffffffu
#define PAD_BIG 1e30f

typedef unsigned long long u64;

__device__ __forceinline__ u64 mul2(u64 a, u64 b) {
    u64 r;
    asm("mul.rn.f32x2 %0, %1, %2;" : "=l"(r) : "l"(a), "l"(b));
    return r;
}
__device__ __forceinline__ u64 fma2(u64 a, u64 b, u64 c) {
    u64 r;
    asm("fma.rn.f32x2 %0, %1, %2, %3;" : "=l"(r) : "l"(a), "l"(b), "l"(c));
    return r;
}

// dot of two 4-dim slices held as packed f32x2 pairs: 2 packed ops + 1 FADD.
__device__ __forceinline__ float dot4p(const ulonglong2& a, const ulonglong2& b) {
    u64 p = mul2(a.x, b.x);
    p = fma2(a.y, b.y, p);
    float lo = __uint_as_float((unsigned)p);
    float hi = __uint_as_float((unsigned)(p >> 32));
    return lo + hi;
}

__device__ __forceinline__ float fast_sigmoid(float x) {
    return 1.0f / (1.0f + __expf(-x));
}

__device__ __forceinline__ ulonglong2 ldg16_off(const char* base, unsigned byte_off) {
    return __ldg(reinterpret_cast<const ulonglong2*>(base + byte_off));
}

// Reduce-scatter 16 values across the 16-lane segment (sub = lane & 15).
__device__ __forceinline__ float rs16(float (&cur)[16], int sub) {
    #pragma unroll
    for (int j = 0; j < 8; j++) {
        float send = (sub & 1) ? cur[j] : cur[j + 8];
        float keep = (sub & 1) ? cur[j + 8] : cur[j];
        cur[j] = keep + __shfl_xor_sync(FULL, send, 1);
    }
    #pragma unroll
    for (int j = 0; j < 4; j++) {
        float send = (sub & 2) ? cur[j] : cur[j + 4];
        float keep = (sub & 2) ? cur[j + 4] : cur[j];
        cur[j] = keep + __shfl_xor_sync(FULL, send, 2);
    }
    #pragma unroll
    for (int j = 0; j < 2; j++) {
        float send = (sub & 4) ? cur[j] : cur[j + 2];
        float keep = (sub & 4) ? cur[j + 2] : cur[j];
        cur[j] = keep + __shfl_xor_sync(FULL, send, 4);
    }
    {
        float send = (sub & 8) ? cur[0] : cur[1];
        float keep = (sub & 8) ? cur[1] : cur[0];
        cur[0] = keep + __shfl_xor_sync(FULL, send, 8);
    }
    return cur[0];
}

// Full per-candidate-pair compute: dots + reductions + mins.
// Returns (star_min, clique) on lanes with sub == 0.
__device__ __forceinline__ float2 process_pair(const ulonglong2& s,
                                               const ulonglong2 (&nv)[SET_SIZE],
                                               int sub) {
    float cur[16];

    // group 0: star (0..7) + diagonal (8..15)
    #pragma unroll
    for (int t = 0; t < SET_SIZE; t++) cur[t] = dot4p(s, nv[t]);
    #pragma unroll
    for (int t = 0; t < SET_SIZE; t++) cur[8 + t] = dot4p(nv[t], nv[t]);

    float v = rs16(cur, sub);
    v = fminf(v, __shfl_xor_sync(FULL, v, 2));
    v = fminf(v, __shfl_xor_sync(FULL, v, 4));
    v = fminf(v, __shfl_xor_sync(FULL, v, 8));
    float star_min = v;                               // even lanes
    float diag_min = __shfl_xor_sync(FULL, v, 1);     // odd-lane min -> even

    // off-diagonal pairs: 28 dots in 2 chunks of 16
    {
        const int PA0[16] = {0,0,0,0,0,0,0, 1,1,1,1,1,1, 2,2,2};
        const int PB0[16] = {1,2,3,4,5,6,7, 2,3,4,5,6,7, 3,4,5};
        #pragma unroll
        for (int k = 0; k < 16; k++) cur[k] = dot4p(nv[PA0[k]], nv[PB0[k]]);
    }
    float p0 = rs16(cur, sub);

    {
        const int PA1[12] = {2,2, 3,3,3,3, 4,4,4, 5,5, 6};
        const int PB1[12] = {6,7, 4,5,6,7, 5,6,7, 6,7, 7};
        #pragma unroll
        for (int k = 0; k < 12; k++) cur[k] = dot4p(nv[PA1[k]], nv[PB1[k]]);
        #pragma unroll
        for (int k = 12; k < 16; k++) cur[k] = PAD_BIG;
    }
    float p1 = rs16(cur, sub);

    float pmin = fminf(p0, p1);
    pmin = fminf(pmin, __shfl_xor_sync(FULL, pmin, 1));
    pmin = fminf(pmin, __shfl_xor_sync(FULL, pmin, 2));
    pmin = fminf(pmin, __shfl_xor_sync(FULL, pmin, 4));
    pmin = fminf(pmin, __shfl_xor_sync(FULL, pmin, 8));

    return make_float2(star_min, fminf(diag_min, pmin));
}

__device__ __forceinline__ void load_pair(const char* nbase, const char* hbase,
                                          const int* __restrict__ h,
                                          const int* __restrict__ X,
                                          int ec, unsigned lane_off,
                                          ulonglong2& s, ulonglong2 (&nv)[SET_SIZE]) {
    const int4* xrow = reinterpret_cast<const int4*>(X + ec * SET_SIZE);
    int4 xa = __ldg(xrow);
    int4 xb = __ldg(xrow + 1);
    int h_idx = __ldg(h + ec);

    s = ldg16_off(hbase, (unsigned)h_idx * ROW_BYTES + lane_off);
    nv[0] = ldg16_off(nbase, (unsigned)xa.x * ROW_BYTES + lane_off);
    nv[1] = ldg16_off(nbase, (unsigned)xa.y * ROW_BYTES + lane_off);
    nv[2] = ldg16_off(nbase, (unsigned)xa.z * ROW_BYTES + lane_off);
    nv[3] = ldg16_off(nbase, (unsigned)xa.w * ROW_BYTES + lane_off);
    nv[4] = ldg16_off(nbase, (unsigned)xb.x * ROW_BYTES + lane_off);
    nv[5] = ldg16_off(nbase, (unsigned)xb.y * ROW_BYTES + lane_off);
    nv[6] = ldg16_off(nbase, (unsigned)xb.z * ROW_BYTES + lane_off);
    nv[7] = ldg16_off(nbase, (unsigned)xb.w * ROW_BYTES + lane_off);
}

__global__ __launch_bounds__(128, 5)
void hyperedge_score_kernel(const float* __restrict__ node_emb,
                            const float* __restrict__ hyper_emb,
                            const int* __restrict__ h,
                            const int* __restrict__ X,
                            float* __restrict__ out,
                            int n_cand)
{
    const int lane = threadIdx.x & 31;
    const int warp = threadIdx.x >> 5;
    const int seg  = lane >> 4;   // candidate within phase (0..1)
    const int sub  = lane & 15;   // float4 slice id       (0..15)

    // Each warp handles 4 candidates: phase A = {base, base+1},
    // phase B = {base+2, base+3}.
    int base = (blockIdx.x * 4 + warp) * 4;
    int eA = base + seg;
    int eB = base + 2 + seg;
    int ecA = min(eA, n_cand - 1);
    int ecB = min(eB, n_cand - 1);

    const char* nbase = reinterpret_cast<const char*>(node_emb);
    const char* hbase = reinterpret_cast<const char*>(hyper_emb);
    const unsigned lane_off = (unsigned)(sub * 16);

    // Issue ALL gathers for both phases up front; phase A's compute hides
    // phase B's L2 latency.
    ulonglong2 sA, sB;
    ulonglong2 nvA[SET_SIZE], nvB[SET_SIZE];
    load_pair(nbase, hbase, h, X, ecA, lane_off, sA, nvA);
    load_pair(nbase, hbase, h, X, ecB, lane_off, sB, nvB);

    float2 rA = process_pair(sA, nvA, sub);
    if (eA < n_cand && sub == 0) {
        reinterpret_cast<float2*>(out)[eA] =
            make_float2(fast_sigmoid(rA.x), fast_sigmoid(rA.y));
    }

    float2 rB = process_pair(sB, nvB, sub);
    if (eB < n_cand && sub == 0) {
        reinterpret_cast<float2*>(out)[eB] =
            make_float2(fast_sigmoid(rB.x), fast_sigmoid(rB.y));
    }
}

extern "C" void kernel_launch(void* const* d_in, const int* in_sizes, int n_in,
                              void* d_out, int out_size) {
    const float* node_emb  = (const float*)d_in[0];
    const float* hyper_emb = (const float*)d_in[1];
    const int*   h         = (const int*)d_in[2];
    const int*   X         = (const int*)d_in[3];
    float*       out       = (float*)d_out;

    const int n_cand = in_sizes[2];

    const int cands_per_block = 16;   // 4 warps * 4 candidates
    const int blocks = (n_cand + cands_per_block - 1) / cands_per_block;

    hyperedge_score_kernel<<<blocks, 128>>>(node_emb, hyper_emb, h, X, out, n_cand);
}

// round 11
// speedup vs baseline: 1.1709x; 1.0825x over previous
#include <cuda_runtime.h>
#include <cuda_bf16.h>

// Problem shapes:
//   node_emb      [100000, 64] f32
//   hyperedge_emb [ 50000, 64] f32
//   h             [200000]      i32
//   X             [200000, 8]   i32
//   out           [200000, 2]   f32
//
// Layout: 16 lanes per candidate (lane owns one float4 = 4 dims, held as a
// ulonglong2 so packed f32x2 pairs come straight out of LDG.128),
// 2 candidates per warp, 128 threads/block.
// Dot products use Blackwell packed f32x2 FMA. Cross-lane sums use
// recursive-halving reduce-scatter (15 shuffles / 16-value group); the
// induced bit-reversal permutation is harmless since every group feeds a
// min. X row loaded as 2x int4 (uniform within segment -> L1 broadcast).
// Registers at 64 (launch_bounds occ=8) -> 32 warps/SM.
//
// This configuration was verified as the local optimum: more warps (56-reg
// cap), persistent CTAs, and 2x intra-warp pipelining all regressed.

#define SET_SIZE 8
#define EMB_DIM  64
#define ROW_BYTES 256
#define FULL 0xffffffffu
#define PAD_BIG 1e30f

typedef unsigned long long u64;

__device__ __forceinline__ u64 mul2(u64 a, u64 b) {
    u64 r;
    asm("mul.rn.f32x2 %0, %1, %2;" : "=l"(r) : "l"(a), "l"(b));
    return r;
}
__device__ __forceinline__ u64 fma2(u64 a, u64 b, u64 c) {
    u64 r;
    asm("fma.rn.f32x2 %0, %1, %2, %3;" : "=l"(r) : "l"(a), "l"(b), "l"(c));
    return r;
}

// dot of two 4-dim slices held as packed f32x2 pairs: 2 packed ops + 1 FADD.
__device__ __forceinline__ float dot4p(const ulonglong2& a, const ulonglong2& b) {
    u64 p = mul2(a.x, b.x);
    p = fma2(a.y, b.y, p);
    float lo = __uint_as_float((unsigned)p);
    float hi = __uint_as_float((unsigned)(p >> 32));
    return lo + hi;
}

__device__ __forceinline__ float fast_sigmoid(float x) {
    return 1.0f / (1.0f + __expf(-x));
}

__device__ __forceinline__ ulonglong2 ldg16_off(const char* base, unsigned byte_off) {
    return __ldg(reinterpret_cast<const ulonglong2*>(base + byte_off));
}

// Reduce-scatter 16 values across the 16-lane segment (sub = lane & 15).
// Afterwards each lane holds the full 16-lane sum of value index bitrev4(sub).
__device__ __forceinline__ float rs16(float (&cur)[16], int sub) {
    #pragma unroll
    for (int j = 0; j < 8; j++) {
        float send = (sub & 1) ? cur[j] : cur[j + 8];
        float keep = (sub & 1) ? cur[j + 8] : cur[j];
        cur[j] = keep + __shfl_xor_sync(FULL, send, 1);
    }
    #pragma unroll
    for (int j = 0; j < 4; j++) {
        float send = (sub & 2) ? cur[j] : cur[j + 4];
        float keep = (sub & 2) ? cur[j + 4] : cur[j];
        cur[j] = keep + __shfl_xor_sync(FULL, send, 2);
    }
    #pragma unroll
    for (int j = 0; j < 2; j++) {
        float send = (sub & 4) ? cur[j] : cur[j + 2];
        float keep = (sub & 4) ? cur[j + 2] : cur[j];
        cur[j] = keep + __shfl_xor_sync(FULL, send, 4);
    }
    {
        float send = (sub & 8) ? cur[0] : cur[1];
        float keep = (sub & 8) ? cur[1] : cur[0];
        cur[0] = keep + __shfl_xor_sync(FULL, send, 8);
    }
    return cur[0];
}

__global__ __launch_bounds__(128, 8)
void hyperedge_score_kernel(const float* __restrict__ node_emb,
                            const float* __restrict__ hyper_emb,
                            const int* __restrict__ h,
                            const int* __restrict__ X,
                            float* __restrict__ out,
                            int n_cand)
{
    const int lane = threadIdx.x & 31;
    const int warp = threadIdx.x >> 5;
    const int seg  = lane >> 4;   // candidate within warp (0..1)
    const int sub  = lane & 15;   // float4 slice id      (0..15)

    int e = (blockIdx.x * 4 + warp) * 2 + seg;
    int ec = min(e, n_cand - 1);

    // Each lane loads its candidate's full X row: 2x int4, uniform within
    // the 16-lane segment (L1 broadcast).
    const int4* xrow = reinterpret_cast<const int4*>(X + ec * SET_SIZE);
    int4 xa = __ldg(xrow);
    int4 xb = __ldg(xrow + 1);
    int h_idx = __ldg(h + ec);

    const char* nbase = reinterpret_cast<const char*>(node_emb);
    const char* hbase = reinterpret_cast<const char*>(hyper_emb);
    const unsigned lane_off = (unsigned)(sub * 16);   // float4 within row

    // Gather src slice + 8 node slices; all loads issued up front (MLP).
    ulonglong2 s = ldg16_off(hbase, (unsigned)h_idx * ROW_BYTES + lane_off);

    ulonglong2 nv[SET_SIZE];
    nv[0] = ldg16_off(nbase, (unsigned)xa.x * ROW_BYTES + lane_off);
    nv[1] = ldg16_off(nbase, (unsigned)xa.y * ROW_BYTES + lane_off);
    nv[2] = ldg16_off(nbase, (unsigned)xa.z * ROW_BYTES + lane_off);
    nv[3] = ldg16_off(nbase, (unsigned)xa.w * ROW_BYTES + lane_off);
    nv[4] = ldg16_off(nbase, (unsigned)xb.x * ROW_BYTES + lane_off);
    nv[5] = ldg16_off(nbase, (unsigned)xb.y * ROW_BYTES + lane_off);
    nv[6] = ldg16_off(nbase, (unsigned)xb.z * ROW_BYTES + lane_off);
    nv[7] = ldg16_off(nbase, (unsigned)xb.w * ROW_BYTES + lane_off);

    float cur[16];

    // ---- group 0: star (indices 0..7) + diagonal (indices 8..15) ----
    #pragma unroll
    for (int t = 0; t < SET_SIZE; t++) cur[t] = dot4p(s, nv[t]);
    #pragma unroll
    for (int t = 0; t < SET_SIZE; t++) cur[8 + t] = dot4p(nv[t], nv[t]);

    float v = rs16(cur, sub);
    // bitrev: even lanes hold star sums, odd lanes hold diagonal sums.
    v = fminf(v, __shfl_xor_sync(FULL, v, 2));
    v = fminf(v, __shfl_xor_sync(FULL, v, 4));
    v = fminf(v, __shfl_xor_sync(FULL, v, 8));
    float star_min = v;                               // valid on even lanes
    float diag_min = __shfl_xor_sync(FULL, v, 1);     // odd lanes' min, now on even

    // ---- off-diagonal pairs: 28 dots in 2 chunks of 16 ----
    {
        const int PA0[16] = {0,0,0,0,0,0,0, 1,1,1,1,1,1, 2,2,2};
        const int PB0[16] = {1,2,3,4,5,6,7, 2,3,4,5,6,7, 3,4,5};
        #pragma unroll
        for (int k = 0; k < 16; k++) cur[k] = dot4p(nv[PA0[k]], nv[PB0[k]]);
    }
    float p0 = rs16(cur, sub);

    {
        const int PA1[12] = {2,2, 3,3,3,3, 4,4,4, 5,5, 6};
        const int PB1[12] = {6,7, 4,5,6,7, 5,6,7, 6,7, 7};
        #pragma unroll
        for (int k = 0; k < 12; k++) cur[k] = dot4p(nv[PA1[k]], nv[PB1[k]]);
        #pragma unroll
        for (int k = 12; k < 16; k++) cur[k] = PAD_BIG;
    }
    float p1 = rs16(cur, sub);

    float pmin = fminf(p0, p1);
    pmin = fminf(pmin, __shfl_xor_sync(FULL, pmin, 1));
    pmin = fminf(pmin, __shfl_xor_sync(FULL, pmin, 2));
    pmin = fminf(pmin, __shfl_xor_sync(FULL, pmin, 4));
    pmin = fminf(pmin, __shfl_xor_sync(FULL, pmin, 8));

    if (e < n_cand && sub == 0) {
        float clique = fminf(diag_min, pmin);
        float2 o = make_float2(fast_sigmoid(star_min), fast_sigmoid(clique));
        reinterpret_cast<float2*>(out)[e] = o;
    }
}

extern "C" void kernel_launch(void* const* d_in, const int* in_sizes, int n_in,
                              void* d_out, int out_size) {
    const float* node_emb  = (const float*)d_in[0];
    const float* hyper_emb = (const float*)d_in[1];
    const int*   h         = (const int*)d_in[2];
    const int*   X         = (const int*)d_in[3];
    float*       out       = (float*)d_out;

    const int n_cand = in_sizes[2];

    const int cands_per_block = 8;    // 4 warps * 2 candidates
    const int blocks = (n_cand + cands_per_block - 1) / cands_per_block;

    hyperedge_score_kernel<<<blocks, 128>>>(node_emb, hyper_emb, h, X, out, n_cand);
}

// round 12
// speedup vs baseline: 1.4657x; 1.2518x over previous
#include <cuda_runtime.h>
#include <cuda_bf16.h>

// Problem shapes:
//   node_emb      [100000, 64] f32
//   hyperedge_emb [ 50000, 64] f32
//   h             [200000]      i32
//   X             [200000, 8]   i32
//   out           [200000, 2]   f32
//
// Layout: 8 lanes per candidate, 4 candidates per warp, 128 threads/block.
// Each lane owns a SPLIT 8-dim slice: dims [4s,4s+4) and [32+4s,32+4s+4),
// so each of the two LDG.128 gather instructions per node covers exactly one
// 128B line per candidate-row (irreducible 2 lines/row).
// Dot products use Blackwell packed f32x2 FMA (4 packed ops + 1 FADD per
// 8-dim partial). Cross-lane sums use recursive-halving reduce-scatter over
// 8 lanes (7 slots per 8-value chunk); every reduction instruction now
// serves 4 candidates instead of 2, halving shuffle cost per candidate.
// Bit-reversal permutation harmless (all groups feed mins).

#define SET_SIZE 8
#define EMB_DIM  64
#define ROW_BYTES 256
#define FULL 0xffffffffu
#define PAD_BIG 1e30f

typedef unsigned long long u64;

__device__ __forceinline__ u64 mul2(u64 a, u64 b) {
    u64 r;
    asm("mul.rn.f32x2 %0, %1, %2;" : "=l"(r) : "l"(a), "l"(b));
    return r;
}
__device__ __forceinline__ u64 fma2(u64 a, u64 b, u64 c) {
    u64 r;
    asm("fma.rn.f32x2 %0, %1, %2, %3;" : "=l"(r) : "l"(a), "l"(b), "l"(c));
    return r;
}

// 8-dim slice held as two 16B chunks (4 packed f32x2 pairs).
struct Slice8 {
    ulonglong2 a;   // dims [4s, 4s+4)
    ulonglong2 b;   // dims [32+4s, 32+4s+4)
};

// partial dot over a lane's 8 dims: 4 packed ops + 1 unpack-add.
__device__ __forceinline__ float dot8p(const Slice8& x, const Slice8& y) {
    u64 p = mul2(x.a.x, y.a.x);
    p = fma2(x.a.y, y.a.y, p);
    p = fma2(x.b.x, y.b.x, p);
    p = fma2(x.b.y, y.b.y, p);
    float lo = __uint_as_float((unsigned)p);
    float hi = __uint_as_float((unsigned)(p >> 32));
    return lo + hi;
}

__device__ __forceinline__ float fast_sigmoid(float x) {
    return 1.0f / (1.0f + __expf(-x));
}

__device__ __forceinline__ Slice8 ld_slice(const char* base, unsigned row_off,
                                           unsigned o0, unsigned o1) {
    Slice8 r;
    r.a = __ldg(reinterpret_cast<const ulonglong2*>(base + row_off + o0));
    r.b = __ldg(reinterpret_cast<const ulonglong2*>(base + row_off + o1));
    return r;
}

// Reduce-scatter 8 values across the 8-lane segment (sub = lane & 7).
// Afterwards each lane holds the full 8-lane sum of value index bitrev3(sub).
__device__ __forceinline__ float rs8(float (&cur)[8], int sub) {
    #pragma unroll
    for (int j = 0; j < 4; j++) {
        float send = (sub & 1) ? cur[j] : cur[j + 4];
        float keep = (sub & 1) ? cur[j + 4] : cur[j];
        cur[j] = keep + __shfl_xor_sync(FULL, send, 1);
    }
    #pragma unroll
    for (int j = 0; j < 2; j++) {
        float send = (sub & 2) ? cur[j] : cur[j + 2];
        float keep = (sub & 2) ? cur[j + 2] : cur[j];
        cur[j] = keep + __shfl_xor_sync(FULL, send, 2);
    }
    {
        float send = (sub & 4) ? cur[0] : cur[1];
        float keep = (sub & 4) ? cur[1] : cur[0];
        cur[0] = keep + __shfl_xor_sync(FULL, send, 4);
    }
    return cur[0];
}

__global__ __launch_bounds__(128, 5)
void hyperedge_score_kernel(const float* __restrict__ node_emb,
                            const float* __restrict__ hyper_emb,
                            const int* __restrict__ h,
                            const int* __restrict__ X,
                            float* __restrict__ out,
                            int n_cand)
{
    const int lane = threadIdx.x & 31;
    const int warp = threadIdx.x >> 5;
    const int seg  = lane >> 3;   // candidate within warp (0..3)
    const int sub  = lane & 7;    // slice id             (0..7)

    int e = (blockIdx.x * 4 + warp) * 4 + seg;
    int ec = min(e, n_cand - 1);

    // Index loads: uniform within each 8-lane segment (L1 broadcast).
    const int4* xrow = reinterpret_cast<const int4*>(X + ec * SET_SIZE);
    int4 xa = __ldg(xrow);
    int4 xb = __ldg(xrow + 1);
    int h_idx = __ldg(h + ec);

    const char* nbase = reinterpret_cast<const char*>(node_emb);
    const char* hbase = reinterpret_cast<const char*>(hyper_emb);
    const unsigned o0 = (unsigned)(sub * 16);        // bytes [0,128) of row
    const unsigned o1 = 128u + (unsigned)(sub * 16); // bytes [128,256)

    // Gather src + 8 node slices; all loads issued up front (MLP = 18).
    Slice8 s = ld_slice(hbase, (unsigned)h_idx * ROW_BYTES, o0, o1);

    Slice8 nv[SET_SIZE];
    nv[0] = ld_slice(nbase, (unsigned)xa.x * ROW_BYTES, o0, o1);
    nv[1] = ld_slice(nbase, (unsigned)xa.y * ROW_BYTES, o0, o1);
    nv[2] = ld_slice(nbase, (unsigned)xa.z * ROW_BYTES, o0, o1);
    nv[3] = ld_slice(nbase, (unsigned)xa.w * ROW_BYTES, o0, o1);
    nv[4] = ld_slice(nbase, (unsigned)xb.x * ROW_BYTES, o0, o1);
    nv[5] = ld_slice(nbase, (unsigned)xb.y * ROW_BYTES, o0, o1);
    nv[6] = ld_slice(nbase, (unsigned)xb.z * ROW_BYTES, o0, o1);
    nv[7] = ld_slice(nbase, (unsigned)xb.w * ROW_BYTES, o0, o1);

    float cur[8];

    // ---- chunk: star <s, n_t> ----
    #pragma unroll
    for (int t = 0; t < SET_SIZE; t++) cur[t] = dot8p(s, nv[t]);
    float star = rs8(cur, sub);
    star = fminf(star, __shfl_xor_sync(FULL, star, 1));
    star = fminf(star, __shfl_xor_sync(FULL, star, 2));
    star = fminf(star, __shfl_xor_sync(FULL, star, 4));

    // ---- chunk: diagonal <n_t, n_t>  (feeds clique min) ----
    #pragma unroll
    for (int t = 0; t < SET_SIZE; t++) cur[t] = dot8p(nv[t], nv[t]);
    float pm = rs8(cur, sub);

    // ---- off-diagonal pairs: 28 dots in 4 chunks of 8 (last padded) ----
    {
        const int PA[8] = {0,0,0,0,0,0,0,1}, PB[8] = {1,2,3,4,5,6,7,2};
        #pragma unroll
        for (int k = 0; k < 8; k++) cur[k] = dot8p(nv[PA[k]], nv[PB[k]]);
        pm = fminf(pm, rs8(cur, sub));
    }
    {
        const int PA[8] = {1,1,1,1,1,2,2,2}, PB[8] = {3,4,5,6,7,3,4,5};
        #pragma unroll
        for (int k = 0; k < 8; k++) cur[k] = dot8p(nv[PA[k]], nv[PB[k]]);
        pm = fminf(pm, rs8(cur, sub));
    }
    {
        const int PA[8] = {2,2,3,3,3,3,4,4}, PB[8] = {6,7,4,5,6,7,5,6};
        #pragma unroll
        for (int k = 0; k < 8; k++) cur[k] = dot8p(nv[PA[k]], nv[PB[k]]);
        pm = fminf(pm, rs8(cur, sub));
    }
    {
        const int PA[4] = {4,5,5,6}, PB[4] = {7,6,7,7};
        #pragma unroll
        for (int k = 0; k < 4; k++) cur[k] = dot8p(nv[PA[k]], nv[PB[k]]);
        #pragma unroll
        for (int k = 4; k < 8; k++) cur[k] = PAD_BIG;
        pm = fminf(pm, rs8(cur, sub));
    }

    // clique min across the 8-lane segment.
    pm = fminf(pm, __shfl_xor_sync(FULL, pm, 1));
    pm = fminf(pm, __shfl_xor_sync(FULL, pm, 2));
    pm = fminf(pm, __shfl_xor_sync(FULL, pm, 4));

    if (e < n_cand && sub == 0) {
        float2 o = make_float2(fast_sigmoid(star), fast_sigmoid(pm));
        reinterpret_cast<float2*>(out)[e] = o;
    }
}

extern "C" void kernel_launch(void* const* d_in, const int* in_sizes, int n_in,
                              void* d_out, int out_size) {
    const float* node_emb  = (const float*)d_in[0];
    const float* hyper_emb = (const float*)d_in[1];
    const int*   h         = (const int*)d_in[2];
    const int*   X         = (const int*)d_in[3];
    float*       out       = (float*)d_out;

    const int n_cand = in_sizes[2];

    const int cands_per_block = 16;   // 4 warps * 4 candidates
    const int blocks = (n_cand + cands_per_block - 1) / cands_per_block;

    hyperedge_score_kernel<<<blocks, 128>>>(node_emb, hyper_emb, h, X, out, n_cand);
}